// round 10
// baseline (speedup 1.0000x reference)
#include <cuda_runtime.h>
#include <math.h>

#define H 4096
#define EPS 1e-5f
#define ROWS_PER_WARP 5
#define GBLOCKS 512                          // 512*8 warps * 5 rows = 20480 rows
#define ROWS_PER_BLOCK_G (8 * ROWS_PER_WARP) // 40
#define EBLOCKS 16
#define ETHR 64                              // 16*64 = 1024 float4 = H/4

// Scratch + accumulators (no device allocation allowed).
__device__ __align__(16) float g_z[5 * H];
__device__ float g_sum[5]   = {0.f, 0.f, 0.f, 0.f, 0.f};
__device__ float g_sumsq[5] = {0.f, 0.f, 0.f, 0.f, 0.f};
__device__ float g_csum   = 0.f;
__device__ float g_csumsq = 0.f;
__device__ unsigned int g_cnt  = 0;
__device__ unsigned int g_done = 0;

__device__ __forceinline__ float sigmoidf_(float x) {
    return 1.0f / (1.0f + __expf(-x));
}
// tanh(x) = 1 - 2/(exp(2x)+1); saturates correctly at +/-inf.
__device__ __forceinline__ float tanhf_(float x) {
    return 1.0f - 2.0f / (__expf(2.0f * x) + 1.0f);
}

// ---------------------------------------------------------------------------
// Kernel 1: GEMV, single-wave perfectly balanced.
// 512 blocks x 256 threads, all resident simultaneously (occ 4 of 148 SMs).
// Each warp computes exactly 5 consecutive rows: zero wave raggedness, zero
// tail. x staged in shared once per block. W streamed with __ldcs.
// Per-part (sum,sumsq) of z via 2-slot shared accumulators (a 40-row block
// can straddle at most one part boundary) + <=4 global atomics per block.
// ---------------------------------------------------------------------------
__global__ __launch_bounds__(256, 4)
void gemv_kernel(const float* __restrict__ h0,
                 const float* __restrict__ h1,
                 const float* __restrict__ W)
{
    __shared__ float xs[2 * H];
    __shared__ float ss[2], sq[2];

    const int tid  = threadIdx.x;
    const int warp = tid >> 5;
    const int lane = tid & 31;

    if (tid < 2) { ss[tid] = 0.f; sq[tid] = 0.f; }

    const float4* h0v = reinterpret_cast<const float4*>(h0);
    const float4* h1v = reinterpret_cast<const float4*>(h1);
    float4* xsv = reinterpret_cast<float4*>(xs);
    #pragma unroll
    for (int i = tid; i < H / 4; i += 256) {
        xsv[i]         = h0v[i];
        xsv[i + H / 4] = h1v[i];
    }
    __syncthreads();

    const int row0     = blockIdx.x * ROWS_PER_BLOCK_G + warp * ROWS_PER_WARP;
    const int part_lo  = (blockIdx.x * ROWS_PER_BLOCK_G) >> 12;   // row/4096

    #pragma unroll
    for (int j = 0; j < ROWS_PER_WARP; j++) {
        const int row = row0 + j;
        const float4* wrow =
            reinterpret_cast<const float4*>(W + (size_t)row * (2 * H));

        float a0 = 0.f, a1 = 0.f, a2 = 0.f, a3 = 0.f;
        #pragma unroll 8
        for (int i = lane; i < (2 * H) / 4; i += 32) {
            float4 w = __ldcs(&wrow[i]);
            float4 x = xsv[i];
            a0 = fmaf(w.x, x.x, a0);
            a1 = fmaf(w.y, x.y, a1);
            a2 = fmaf(w.z, x.z, a2);
            a3 = fmaf(w.w, x.w, a3);
        }
        float s = (a0 + a1) + (a2 + a3);
        #pragma unroll
        for (int off = 16; off > 0; off >>= 1)
            s += __shfl_down_sync(0xffffffffu, s, off);

        if (lane == 0) {
            g_z[row] = s;
            const int e = (row >> 12) - part_lo;   // 0 or 1
            atomicAdd(&ss[e], s);
            atomicAdd(&sq[e], s * s);
        }
    }
    __syncthreads();

    if (tid == 0) {
        atomicAdd(&g_sum[part_lo],   ss[0]);
        atomicAdd(&g_sumsq[part_lo], sq[0]);
        const int part_hi = (blockIdx.x * ROWS_PER_BLOCK_G + ROWS_PER_BLOCK_G - 1) >> 12;
        if (part_hi != part_lo) {
            atomicAdd(&g_sum[part_hi],   ss[1]);
            atomicAdd(&g_sumsq[part_hi], sq[1]);
        }
    }
}

// ---------------------------------------------------------------------------
// Kernel 2: epilogue, 16 CTAs x 64 threads (identical to the 108.7us best).
// ---------------------------------------------------------------------------
__global__ __launch_bounds__(ETHR, 1)
void epilogue_kernel(const float* __restrict__ c0,
                     const float* __restrict__ c1,
                     const float* __restrict__ ffio_g,
                     const float* __restrict__ ffio_b,
                     const float* __restrict__ u_g,
                     const float* __restrict__ u_b,
                     const float* __restrict__ c_g,
                     const float* __restrict__ c_b,
                     float* __restrict__ out)
{
    const int t    = threadIdx.x;   // 0..63
    const int warp = t >> 5;
    const int lane = t & 31;
    const int g    = blockIdx.x * ETHR + t;   // float4 index 0..1023

    __shared__ float red_s[2], red_q[2];
    __shared__ float s_mc, s_rc;

    float m5[5], r5[5];
    #pragma unroll
    for (int p = 0; p < 5; p++) {
        float mean = g_sum[p] * (1.0f / H);
        float var  = g_sumsq[p] * (1.0f / H) - mean * mean;
        m5[p] = mean;
        r5[p] = rsqrtf(var + EPS);
    }

    const float4* gz4 = reinterpret_cast<const float4*>(g_z);

    float v[5][4];
    #pragma unroll
    for (int p = 0; p < 5; p++) {
        float4 vv = gz4[p * (H / 4) + g];
        v[p][0] = vv.x; v[p][1] = vv.y; v[p][2] = vv.z; v[p][3] = vv.w;
    }

    float gate[4][4];
    #pragma unroll
    for (int p = 0; p < 4; p++) {
        float4 gv = reinterpret_cast<const float4*>(ffio_g + p * H)[g];
        float4 bv = reinterpret_cast<const float4*>(ffio_b + p * H)[g];
        float ga[4] = {gv.x, gv.y, gv.z, gv.w};
        float ba[4] = {bv.x, bv.y, bv.z, bv.w};
        float m = m5[p], r = r5[p];
        #pragma unroll
        for (int k = 0; k < 4; k++)
            gate[p][k] = sigmoidf_(fmaf((v[p][k] - m) * r, ga[k], ba[k]));
    }

    float uval[4];
    {
        float4 gv = reinterpret_cast<const float4*>(u_g)[g];
        float4 bv = reinterpret_cast<const float4*>(u_b)[g];
        float m = m5[4], r = r5[4];
        uval[0] = tanhf_(fmaf((v[4][0] - m) * r, gv.x, bv.x));
        uval[1] = tanhf_(fmaf((v[4][1] - m) * r, gv.y, bv.y));
        uval[2] = tanhf_(fmaf((v[4][2] - m) * r, gv.z, bv.z));
        uval[3] = tanhf_(fmaf((v[4][3] - m) * r, gv.w, bv.w));
    }

    float4 c0v = reinterpret_cast<const float4*>(c0)[g];
    float4 c1v = reinterpret_cast<const float4*>(c1)[g];
    float c0a[4] = {c0v.x, c0v.y, c0v.z, c0v.w};
    float c1a[4] = {c1v.x, c1v.y, c1v.z, c1v.w};

    float cell[4];
    #pragma unroll
    for (int k = 0; k < 4; k++)
        cell[k] = fmaf(gate[2][k], uval[k],
                  fmaf(gate[0][k], c0a[k], gate[1][k] * c1a[k]));

    {
        float s = (cell[0] + cell[1]) + (cell[2] + cell[3]);
        float q = fmaf(cell[0], cell[0], fmaf(cell[1], cell[1],
                  fmaf(cell[2], cell[2], cell[3] * cell[3])));
        #pragma unroll
        for (int off = 16; off > 0; off >>= 1) {
            s += __shfl_down_sync(0xffffffffu, s, off);
            q += __shfl_down_sync(0xffffffffu, q, off);
        }
        if (lane == 0) { red_s[warp] = s; red_q[warp] = q; }
    }
    __syncthreads();

    if (t == 0) {
        atomicAdd(&g_csum,   red_s[0] + red_s[1]);
        atomicAdd(&g_csumsq, red_q[0] + red_q[1]);
        __threadfence();
        atomicAdd(&g_cnt, 1u);
        while (*((volatile unsigned int*)&g_cnt) < EBLOCKS)
            __nanosleep(32);
        __threadfence();
        float cs = atomicAdd(&g_csum,   0.0f);
        float cq = atomicAdd(&g_csumsq, 0.0f);
        float mean = cs * (1.0f / H);
        float var  = cq * (1.0f / H) - mean * mean;
        s_mc = mean;
        s_rc = rsqrtf(var + EPS);
    }
    __syncthreads();

    const float m = s_mc, r = s_rc;
    float4 cgv = reinterpret_cast<const float4*>(c_g)[g];
    float4 cbv = reinterpret_cast<const float4*>(c_b)[g];
    float cga[4] = {cgv.x, cgv.y, cgv.z, cgv.w};
    float cba[4] = {cbv.x, cbv.y, cbv.z, cbv.w};

    float4 hid, ncl;
    float nc[4], hd[4];
    #pragma unroll
    for (int k = 0; k < 4; k++) {
        nc[k] = fmaf((cell[k] - m) * r, cga[k], cba[k]);
        hd[k] = gate[3][k] * tanhf_(nc[k]);
    }
    hid.x = hd[0]; hid.y = hd[1]; hid.z = hd[2]; hid.w = hd[3];
    ncl.x = nc[0]; ncl.y = nc[1]; ncl.z = nc[2]; ncl.w = nc[3];

    reinterpret_cast<float4*>(out)[g]     = hid;   // new_hidden
    reinterpret_cast<float4*>(out + H)[g] = ncl;   // new_cell

    // Last block resets all cross-launch state for graph replay.
    __syncthreads();
    if (t == 0) {
        unsigned int prev = atomicAdd(&g_done, 1u);
        if (prev == EBLOCKS - 1) {
            g_cnt = 0; g_done = 0;
            g_csum = 0.f; g_csumsq = 0.f;
            #pragma unroll
            for (int p = 0; p < 5; p++) { g_sum[p] = 0.f; g_sumsq[p] = 0.f; }
        }
    }
}

// ---------------------------------------------------------------------------
// Inputs (metadata order): 0=h0, 1=c0, 2=h1, 3=c1, 4=W,
//   5=ffio_g(4H), 6=ffio_b(4H), 7=u_g, 8=u_b, 9=c_g, 10=c_b
// Output: [new_hidden(4096); new_cell(4096)] fp32
// ---------------------------------------------------------------------------
extern "C" void kernel_launch(void* const* d_in, const int* in_sizes, int n_in,
                              void* d_out, int out_size)
{
    const float* h0     = (const float*)d_in[0];
    const float* c0     = (const float*)d_in[1];
    const float* h1     = (const float*)d_in[2];
    const float* c1     = (const float*)d_in[3];
    const float* W      = (const float*)d_in[4];
    const float* ffio_g = (const float*)d_in[5];
    const float* ffio_b = (const float*)d_in[6];
    const float* u_g    = (const float*)d_in[7];
    const float* u_b    = (const float*)d_in[8];
    const float* c_g    = (const float*)d_in[9];
    const float* c_b    = (const float*)d_in[10];
    float* out = (float*)d_out;

    gemv_kernel<<<GBLOCKS, 256>>>(h0, h1, W);
    epilogue_kernel<<<EBLOCKS, ETHR>>>(c0, c1, ffio_g, ffio_b,
                                       u_g, u_b, c_g, c_b, out);
}

// round 11
// speedup vs baseline: 1.0419x; 1.0419x over previous
#include <cuda_runtime.h>
#include <math.h>

#define H 4096
#define EPS 1e-5f
#define ROWS_PER_BLOCK 8
#define NGEMV (5 * H / ROWS_PER_BLOCK)   // 2560, 512 blocks per z-part
#define EBLOCKS 16
#define ETHR 64                           // 16*64 = 1024 float4 = H/4

// Scratch + accumulators (no device allocation allowed).
__device__ __align__(16) float g_z[5 * H];
__device__ float g_sum[5]   = {0.f, 0.f, 0.f, 0.f, 0.f};
__device__ float g_sumsq[5] = {0.f, 0.f, 0.f, 0.f, 0.f};
__device__ float g_csum   = 0.f;
__device__ float g_csumsq = 0.f;
__device__ unsigned int g_ready = 0;   // gemv blocks completed
__device__ unsigned int g_cnt   = 0;   // epilogue blocks at cell-LN barrier
__device__ unsigned int g_done  = 0;   // epilogue blocks finished

__device__ __forceinline__ float sigmoidf_(float x) {
    return 1.0f / (1.0f + __expf(-x));
}
// tanh(x) = 1 - 2/(exp(2x)+1); saturates correctly at +/-inf.
__device__ __forceinline__ float tanhf_(float x) {
    return 1.0f - 2.0f / (__expf(2.0f * x) + 1.0f);
}

// ---------------------------------------------------------------------------
// Kernel 1: GEMV (exact R5 structure, best measured ~98.7us) + release signal.
// z[r] = dot(W[r, 0:2H], [h0;h1]); one warp per row; x staged in shared;
// W streamed with __ldcs. Per-part (sum,sumsq) via 2 atomics per block, then
// a single-thread device-scope release (fence is cumulative over the block's
// prior stores because of the preceding __syncthreads).
// ---------------------------------------------------------------------------
__global__ __launch_bounds__(256, 4)
void gemv_kernel(const float* __restrict__ h0,
                 const float* __restrict__ h1,
                 const float* __restrict__ W)
{
    __shared__ __align__(16) float xs[2 * H];
    __shared__ float rs[8], rq[8];

    const int tid = threadIdx.x;

    const float4* h0v = reinterpret_cast<const float4*>(h0);
    const float4* h1v = reinterpret_cast<const float4*>(h1);
    float4* xsv = reinterpret_cast<float4*>(xs);
    #pragma unroll
    for (int i = tid; i < H / 4; i += 256) {
        xsv[i]         = h0v[i];
        xsv[i + H / 4] = h1v[i];
    }
    __syncthreads();

    const int warp = tid >> 5;
    const int lane = tid & 31;
    const int row  = blockIdx.x * ROWS_PER_BLOCK + warp;

    const float4* wrow = reinterpret_cast<const float4*>(W + (size_t)row * (2 * H));

    float a0 = 0.f, a1 = 0.f, a2 = 0.f, a3 = 0.f;
    #pragma unroll 8
    for (int i = lane; i < (2 * H) / 4; i += 32) {
        float4 w = __ldcs(&wrow[i]);
        float4 x = xsv[i];
        a0 = fmaf(w.x, x.x, a0);
        a1 = fmaf(w.y, x.y, a1);
        a2 = fmaf(w.z, x.z, a2);
        a3 = fmaf(w.w, x.w, a3);
    }
    float s = (a0 + a1) + (a2 + a3);
    #pragma unroll
    for (int off = 16; off > 0; off >>= 1)
        s += __shfl_down_sync(0xffffffffu, s, off);

    if (lane == 0) {
        g_z[row] = s;
        rs[warp] = s;
        rq[warp] = s * s;
    }
    __syncthreads();

    if (tid == 0) {
        float bs = 0.f, bq = 0.f;
        #pragma unroll
        for (int w = 0; w < 8; w++) { bs += rs[w]; bq += rq[w]; }
        const int part = blockIdx.x >> 9;     // 512 blocks per part
        atomicAdd(&g_sum[part],   bs);
        atomicAdd(&g_sumsq[part], bq);
        __threadfence();                      // cumulative release of block's
        atomicAdd(&g_ready, 1u);              // z-stores + stat atomics
    }
}

// ---------------------------------------------------------------------------
// Kernel 2: epilogue, 16 CTAs x 64 threads, launched CONCURRENTLY (graph
// fork). Prefetches all GEMV-independent params into registers, spins on
// g_ready, then runs the z-dependent tail (L2-hot). Consumer L1 holds no
// stale copies of producer data (first touch is after the acquire).
// ---------------------------------------------------------------------------
__global__ __launch_bounds__(ETHR, 1)
void epilogue_kernel(const float* __restrict__ c0,
                     const float* __restrict__ c1,
                     const float* __restrict__ ffio_g,
                     const float* __restrict__ ffio_b,
                     const float* __restrict__ u_g,
                     const float* __restrict__ u_b,
                     const float* __restrict__ c_g,
                     const float* __restrict__ c_b,
                     float* __restrict__ out)
{
    const int t    = threadIdx.x;   // 0..63
    const int warp = t >> 5;
    const int lane = t & 31;
    const int g    = blockIdx.x * ETHR + t;   // float4 index 0..1023

    __shared__ float red_s[2], red_q[2];
    __shared__ float s_mc, s_rc;

    // ---- Prefetch GEMV-independent inputs (overlaps the GEMV stream) -------
    float4 fg[4], fb[4];
    #pragma unroll
    for (int p = 0; p < 4; p++) {
        fg[p] = reinterpret_cast<const float4*>(ffio_g + p * H)[g];
        fb[p] = reinterpret_cast<const float4*>(ffio_b + p * H)[g];
    }
    float4 ugv = reinterpret_cast<const float4*>(u_g)[g];
    float4 ubv = reinterpret_cast<const float4*>(u_b)[g];
    float4 c0v = reinterpret_cast<const float4*>(c0)[g];
    float4 c1v = reinterpret_cast<const float4*>(c1)[g];
    float4 cgv = reinterpret_cast<const float4*>(c_g)[g];
    float4 cbv = reinterpret_cast<const float4*>(c_b)[g];

    // ---- Acquire: wait for all gemv blocks ---------------------------------
    if (t == 0) {
        while (*((volatile unsigned int*)&g_ready) < (unsigned)NGEMV)
            __nanosleep(64);
    }
    __syncthreads();
    __threadfence();    // sc fence: subsequent reads see producers' writes

    // Part statistics (fully accumulated once g_ready hit NGEMV).
    float m5[5], r5[5];
    #pragma unroll
    for (int p = 0; p < 5; p++) {
        float mean = g_sum[p] * (1.0f / H);
        float var  = g_sumsq[p] * (1.0f / H) - mean * mean;
        m5[p] = mean;
        r5[p] = rsqrtf(var + EPS);
    }

    const float4* gz4 = reinterpret_cast<const float4*>(g_z);

    float v[5][4];
    #pragma unroll
    for (int p = 0; p < 5; p++) {
        float4 vv = gz4[p * (H / 4) + g];
        v[p][0] = vv.x; v[p][1] = vv.y; v[p][2] = vv.z; v[p][3] = vv.w;
    }

    float gate[4][4];
    #pragma unroll
    for (int p = 0; p < 4; p++) {
        float ga[4] = {fg[p].x, fg[p].y, fg[p].z, fg[p].w};
        float ba[4] = {fb[p].x, fb[p].y, fb[p].z, fb[p].w};
        float m = m5[p], r = r5[p];
        #pragma unroll
        for (int k = 0; k < 4; k++)
            gate[p][k] = sigmoidf_(fmaf((v[p][k] - m) * r, ga[k], ba[k]));
    }

    float uval[4];
    {
        float m = m5[4], r = r5[4];
        uval[0] = tanhf_(fmaf((v[4][0] - m) * r, ugv.x, ubv.x));
        uval[1] = tanhf_(fmaf((v[4][1] - m) * r, ugv.y, ubv.y));
        uval[2] = tanhf_(fmaf((v[4][2] - m) * r, ugv.z, ubv.z));
        uval[3] = tanhf_(fmaf((v[4][3] - m) * r, ugv.w, ubv.w));
    }

    float c0a[4] = {c0v.x, c0v.y, c0v.z, c0v.w};
    float c1a[4] = {c1v.x, c1v.y, c1v.z, c1v.w};

    float cell[4];
    #pragma unroll
    for (int k = 0; k < 4; k++)
        cell[k] = fmaf(gate[2][k], uval[k],
                  fmaf(gate[0][k], c0a[k], gate[1][k] * c1a[k]));

    // Block partial (sum, sumsq) of cell
    {
        float s = (cell[0] + cell[1]) + (cell[2] + cell[3]);
        float q = fmaf(cell[0], cell[0], fmaf(cell[1], cell[1],
                  fmaf(cell[2], cell[2], cell[3] * cell[3])));
        #pragma unroll
        for (int off = 16; off > 0; off >>= 1) {
            s += __shfl_down_sync(0xffffffffu, s, off);
            q += __shfl_down_sync(0xffffffffu, q, off);
        }
        if (lane == 0) { red_s[warp] = s; red_q[warp] = q; }
    }
    __syncthreads();

    // Cross-block (16 blocks) cell-LN reduction.
    if (t == 0) {
        atomicAdd(&g_csum,   red_s[0] + red_s[1]);
        atomicAdd(&g_csumsq, red_q[0] + red_q[1]);
        __threadfence();
        atomicAdd(&g_cnt, 1u);
        while (*((volatile unsigned int*)&g_cnt) < EBLOCKS)
            __nanosleep(32);
        __threadfence();
        float cs = atomicAdd(&g_csum,   0.0f);
        float cq = atomicAdd(&g_csumsq, 0.0f);
        float mean = cs * (1.0f / H);
        float var  = cq * (1.0f / H) - mean * mean;
        s_mc = mean;
        s_rc = rsqrtf(var + EPS);
    }
    __syncthreads();

    // Final LN on cell + outputs
    const float m = s_mc, r = s_rc;
    float cga[4] = {cgv.x, cgv.y, cgv.z, cgv.w};
    float cba[4] = {cbv.x, cbv.y, cbv.z, cbv.w};

    float4 hid, ncl;
    float nc[4], hd[4];
    #pragma unroll
    for (int k = 0; k < 4; k++) {
        nc[k] = fmaf((cell[k] - m) * r, cga[k], cba[k]);
        hd[k] = gate[3][k] * tanhf_(nc[k]);
    }
    hid.x = hd[0]; hid.y = hd[1]; hid.z = hd[2]; hid.w = hd[3];
    ncl.x = nc[0]; ncl.y = nc[1]; ncl.z = nc[2]; ncl.w = nc[3];

    reinterpret_cast<float4*>(out)[g]     = hid;   // new_hidden
    reinterpret_cast<float4*>(out + H)[g] = ncl;   // new_cell

    // Last epilogue block resets all cross-launch state for graph replay.
    __syncthreads();
    if (t == 0) {
        unsigned int prev = atomicAdd(&g_done, 1u);
        if (prev == EBLOCKS - 1) {
            g_ready = 0; g_cnt = 0; g_done = 0;
            g_csum = 0.f; g_csumsq = 0.f;
            #pragma unroll
            for (int p = 0; p < 5; p++) { g_sum[p] = 0.f; g_sumsq[p] = 0.f; }
        }
    }
}

// ---------------------------------------------------------------------------
// Launch: fork/join so the two kernels run CONCURRENTLY inside the graph.
// The epilogue's in-kernel spin on g_ready provides the data dependency.
// Inputs (metadata order): 0=h0, 1=c0, 2=h1, 3=c1, 4=W,
//   5=ffio_g(4H), 6=ffio_b(4H), 7=u_g, 8=u_b, 9=c_g, 10=c_b
// Output: [new_hidden(4096); new_cell(4096)] fp32
// ---------------------------------------------------------------------------
extern "C" void kernel_launch(void* const* d_in, const int* in_sizes, int n_in,
                              void* d_out, int out_size)
{
    const float* h0     = (const float*)d_in[0];
    const float* c0     = (const float*)d_in[1];
    const float* h1     = (const float*)d_in[2];
    const float* c1     = (const float*)d_in[3];
    const float* W      = (const float*)d_in[4];
    const float* ffio_g = (const float*)d_in[5];
    const float* ffio_b = (const float*)d_in[6];
    const float* u_g    = (const float*)d_in[7];
    const float* u_b    = (const float*)d_in[8];
    const float* c_g    = (const float*)d_in[9];
    const float* c_b    = (const float*)d_in[10];
    float* out = (float*)d_out;

    cudaStream_t s2;
    cudaEvent_t ev_fork, ev_join;
    cudaStreamCreateWithFlags(&s2, cudaStreamNonBlocking);
    cudaEventCreateWithFlags(&ev_fork, cudaEventDisableTiming);
    cudaEventCreateWithFlags(&ev_join, cudaEventDisableTiming);

    // Fork: bring s2 into the captured graph.
    cudaEventRecord(ev_fork, 0);
    cudaStreamWaitEvent(s2, ev_fork, 0);

    gemv_kernel<<<NGEMV, 256>>>(h0, h1, W);                       // stream 0
    epilogue_kernel<<<EBLOCKS, ETHR, 0, s2>>>(c0, c1, ffio_g, ffio_b,
                                              u_g, u_b, c_g, c_b, out);

    // Join back to the main stream.
    cudaEventRecord(ev_join, s2);
    cudaStreamWaitEvent(0, ev_join, 0);
}